// round 16
// baseline (speedup 1.0000x reference)
#include <cuda_runtime.h>
#include <math.h>

#define RES       256
#define NPIX      (RES*RES)       // 65536 pixels per camera
#define NQUAD     (NPIX/4)        // 16384 float4-groups per camera
#define NCAM      32
#define NB        64
#define CAMCHUNK  55              // grid 1760 <= 12*148=1776 -> single wave @12 blocks/SM
#define TPB       64
#define NWARP     (TPB/32)        // 2
#define ROWS      74              // 0..2: bins -3..-1 (dummy); 3..66: bins 0..63; 67..73: dummy-high

__global__ void spad_zero_out(float* __restrict__ out) {
    int i = blockIdx.x * blockDim.x + threadIdx.x;
    if (i < NCAM * NB) out[i] = 0.0f;
}

__device__ __forceinline__ void process_quad(
    int q, const float4* __restrict__ n4, const float4* __restrict__ p4,
    float* Wbase, float radC, float inv2sig2, float halfInvBin,
    float gridCS, float gridStep)
{
    float4 nA = __ldcs(&n4[q*3+0]), nB = __ldcs(&n4[q*3+1]), nC = __ldcs(&n4[q*3+2]);
    float4 pA = __ldcs(&p4[q*3+0]), pB = __ldcs(&p4[q*3+1]), pC = __ldcs(&p4[q*3+2]);

    float n_[12], p_[12];
    *(float4*)&n_[0] = nA; *(float4*)&n_[4] = nB; *(float4*)&n_[8] = nC;
    *(float4*)&p_[0] = pA; *(float4*)&p_[4] = pB; *(float4*)&p_[8] = pC;

    const int   row  = q >> 6;              // pixel row (4 px share a row)
    const int   col0 = (q & 63) << 2;       // first column of the quad
    const float yg   = fmaf((float)row, gridStep, -gridCS);
    const float yg21 = fmaf(yg, yg, 1.0f);

    #pragma unroll
    for (int u = 0; u < 4; ++u) {
        const float nx = n_[3*u], ny = n_[3*u+1], nz = n_[3*u+2];
        const float px = p_[3*u], py = p_[3*u+1], pz = p_[3*u+2];

        const float xg  = fmaf((float)(col0 + u), gridStep, -gridCS);
        const float cm  = rsqrtf(fmaf(xg, xg, yg21));            // MUFU.RSQ
        const float tdn = nz + yg * ny - xg * nx;
        float dots = fminf(fmaxf(tdn * cm, 0.0f), 1.0f);

        const float lx = px - 0.002f;     // 2 * camera_sensor_distance
        const float ly = py;
        const float lz = pz;
        const float lxy2 = lx*lx + ly*ly;
        const float ld2  = lxy2 + lz*lz;

        const float rld   = rsqrtf(ld2);                         // MUFU.RSQ
        const float ld    = ld2 * rld;
        const float ild2  = rld * rld;
        const float ilz2  = __fdividef(1.0f, lz * lz);           // MUFU.RCP
        const float lm    = __expf(-lxy2 * inv2sig2 * ilz2);     // MUFU.EX2

        // pd = |p| without another sqrt: pd^2 = ld^2 + 0.004*lx + 4e-6
        const float t   = fmaf(0.004f, lx, 4.0e-6f) * rld;       // ld*u
        const float uu  = t * rld;                               // u ~ 5e-3
        const float pd  = ld + t * fmaf(-0.125f, uu, 0.5f);      // 2nd-order Taylor

        const float cm3 = cm * cm * cm;
        const float r   = dots * lm * cm3 * radC * ild2;
        const float d   = (pd + ld) * halfInvBin;                // bin coordinate (>=0)

        const int kc = __float2int_rd(d);

        // 7-bin window kc-3..kc+3; D_j = 1 + G*e^{3j}, independent ffma-imm.
        const float G = __expf(3.0f * ((float)kc - d - 2.0f));   // MUFU.EX2
        const float D0 = fmaf(G, 1.0f,          1.0f);
        const float D1 = fmaf(G, 20.085537f,    1.0f);
        const float D2 = fmaf(G, 403.42877f,    1.0f);
        const float D3 = fmaf(G, 8103.0840f,    1.0f);
        const float D4 = fmaf(G, 162754.79f,    1.0f);
        const float D5 = fmaf(G, 3269017.4f,    1.0f);
        const float D6 = fmaf(G, 65659968.0f,   1.0f);

        // Split Montgomery: two short independent chains (one RCP each)
        const float PA1 = D0 * D1;
        const float PA2 = PA1 * D2;
        const float PA3 = PA2 * D3;                              // <= ~60
        const float PB1 = D4 * D5;
        const float PB2 = PB1 * D6;                              // <= ~5e11

        float RA = __fdividef(r, PA3);                           // MUFU.RCP
        float RB = __fdividef(r, PB2);                           // MUFU.RCP
        const float S3 = PA2 * RA;  RA *= D3;
        const float S6 = PB1 * RB;  RB *= D6;
        const float S2 = PA1 * RA;  RA *= D2;
        const float S5 = D4  * RB;  RB *= D5;
        const float S1 = D0  * RA;  RA *= D1;
        const float S4 = RB;                                     // r/D4
        const float S0 = RA;                                     // r/D0

        // BRANCH-FREE scatter: bin b -> row b+3. Window rows kc..kc+6.
        // kc >= 0 always; clamp base so overflow windows land in dummy rows
        // 67..73. Telescoped diffs are ~0 outside the window, so dummy mass
        // never reaches a real bin.
        const int base = min(kc, 67);
        float* w = Wbase + (base << 5);
        w[0*32] += r  - S0;
        w[1*32] += S0 - S1;
        w[2*32] += S1 - S2;
        w[3*32] += S2 - S3;
        w[4*32] += S3 - S4;
        w[5*32] += S4 - S5;
        w[6*32] += S5 - S6;
    }
}

__global__ __launch_bounds__(TPB, 12) void spad_main(
    const float* __restrict__ normals,
    const float* __restrict__ inter,
    float* __restrict__ out,
    float radC, float inv2sig2, float halfInvBin,
    float gridCS, float gridStep)
{
    // per-(warp,lane) private difference-histograms: bank == lane, conflict-free
    __shared__ float sh[NWARP][ROWS][32];

    const int tid  = threadIdx.x;
    const int lane = tid & 31;
    const int wid  = tid >> 5;

    for (int i = tid; i < NWARP * ROWS * 32; i += TPB)
        ((float*)sh)[i] = 0.0f;
    __syncthreads();

    const int cam   = blockIdx.x / CAMCHUNK;
    const int chunk = blockIdx.x % CAMCHUNK;
    const int qs    = (NQUAD * chunk)       / CAMCHUNK;
    const int qe    = (NQUAD * (chunk + 1)) / CAMCHUNK;

    const float4* n4 = (const float4*)(normals + (size_t)cam * NPIX * 3);
    const float4* p4 = (const float4*)(inter   + (size_t)cam * NPIX * 3);

    float* Wbase = &sh[wid][0][lane];

    // 2x unrolled: 8 pixels (two quads) in flight per thread
    int q = qs + tid;
    for (; q + TPB < qe; q += 2 * TPB) {
        process_quad(q,       n4, p4, Wbase, radC, inv2sig2, halfInvBin, gridCS, gridStep);
        process_quad(q + TPB, n4, p4, Wbase, radC, inv2sig2, halfInvBin, gridCS, gridStep);
    }
    if (q < qe)
        process_quad(q, n4, p4, Wbase, radC, inv2sig2, halfInvBin, gridCS, gridStep);

    __syncthreads();

    // fold warp 1 into warp 0
    float* s0 = (float*)sh;
    for (int i = tid; i < ROWS * 32; i += TPB)
        s0[i] += s0[i + ROWS * 32];
    __syncthreads();

    // lane-rotated conflict-free reduction; bin k lives at row k+3
    if (tid < NB) {
        float s = 0.0f;
        #pragma unroll
        for (int l = 0; l < 32; ++l)
            s += sh[0][tid + 3][(l + tid) & 31];
        atomicAdd(&out[cam * NB + tid], s);
    }
}

extern "C" void kernel_launch(void* const* d_in, const int* in_sizes, int n_in,
                              void* d_out, int out_size) {
    const float* normals = (const float*)d_in[0];   // [32,256,256,3]
    const float* inter   = (const float*)d_in[1];   // [32,256,256,3]
    float* out = (float*)d_out;                     // [32,64]

    const double fov    = 33.0 * M_PI / 180.0;
    const double width  = 2.0 * tan(fov / 2.0);
    const float  radC   = (float)(width * width / (M_PI * (double)NPIX));
    const double sig    = tan(21.5 * M_PI / 180.0) / 1.4;
    const float  inv2s2 = (float)(1.0 / (2.0 * sig * sig));
    const float  hib    = (float)(0.5 / 0.0136);    // (1/2) / bin_size

    // film/cos grid: linspace(-cs, cs, 256), cs = tan(fov/2)*(1 - 1/256)
    const float cs   = (float)(tan(fov / 2.0) * (1.0 - 1.0 / RES));
    const float step = (float)(2.0 * (double)cs / (RES - 1));

    spad_zero_out<<<(NCAM * NB + 255) / 256, 256>>>(out);
    spad_main<<<NCAM * CAMCHUNK, TPB>>>(normals, inter, out,
                                        radC, inv2s2, hib, cs, step);
    (void)in_sizes; (void)n_in; (void)out_size;
}

// round 17
// speedup vs baseline: 1.4177x; 1.4177x over previous
#include <cuda_runtime.h>
#include <math.h>

#define RES       256
#define NPIX      (RES*RES)       // 65536 pixels per camera
#define NQUAD     (NPIX/4)        // 16384 float4-groups per camera
#define NCAM      32
#define NB        64
#define CAMCHUNK  55              // grid 1760 <= 12*148=1776 -> single wave @12 blocks/SM
#define TPB       64
#define NWARP     (TPB/32)        // 2
#define ROWS      66              // row 0: dummy(k<0); 1..64: bins 0..63; 65: dummy(k>=64)
#define UNITS     (2*CAMCHUNK-1)  // chunk 0 gets 1 unit (half-size), others 2 units

// cross-block flag/counter scratch (zero-initialized; restored each launch)
__device__ unsigned int g_ready[NCAM];
__device__ unsigned int g_cnt[NCAM];

__device__ __forceinline__ void process_quad(
    int q, const float4* __restrict__ n4, const float4* __restrict__ p4,
    float* Wbase, float radC, float inv2sig2, float halfInvBin,
    float gridCS, float gridStep)
{
    float4 nA = __ldcs(&n4[q*3+0]), nB = __ldcs(&n4[q*3+1]), nC = __ldcs(&n4[q*3+2]);
    float4 pA = __ldcs(&p4[q*3+0]), pB = __ldcs(&p4[q*3+1]), pC = __ldcs(&p4[q*3+2]);

    float n_[12], p_[12];
    *(float4*)&n_[0] = nA; *(float4*)&n_[4] = nB; *(float4*)&n_[8] = nC;
    *(float4*)&p_[0] = pA; *(float4*)&p_[4] = pB; *(float4*)&p_[8] = pC;

    const int   row  = q >> 6;              // pixel row (4 px share a row)
    const int   col0 = (q & 63) << 2;       // first column of the quad
    const float yg   = fmaf((float)row, gridStep, -gridCS);
    const float yg21 = fmaf(yg, yg, 1.0f);

    #pragma unroll
    for (int u = 0; u < 4; ++u) {
        const float nx = n_[3*u], ny = n_[3*u+1], nz = n_[3*u+2];
        const float px = p_[3*u], py = p_[3*u+1], pz = p_[3*u+2];

        const float xg  = fmaf((float)(col0 + u), gridStep, -gridCS);
        const float cm  = rsqrtf(fmaf(xg, xg, yg21));            // MUFU.RSQ
        const float tdn = nz + yg * ny - xg * nx;
        float dots = fminf(fmaxf(tdn * cm, 0.0f), 1.0f);

        const float lx = px - 0.002f;     // 2 * camera_sensor_distance
        const float ly = py;
        const float lz = pz;
        const float lxy2 = lx*lx + ly*ly;
        const float ld2  = lxy2 + lz*lz;

        const float rld   = rsqrtf(ld2);                         // MUFU.RSQ
        const float ld    = ld2 * rld;
        const float ild2  = rld * rld;
        const float ilz2  = __fdividef(1.0f, lz * lz);           // MUFU.RCP
        const float lm    = __expf(-lxy2 * inv2sig2 * ilz2);     // MUFU.EX2

        // pd = |p| without another sqrt: pd^2 = ld^2 + 0.004*lx + 4e-6
        const float t   = fmaf(0.004f, lx, 4.0e-6f) * rld;       // ld*u
        const float uu  = t * rld;                               // u ~ 5e-3
        const float pd  = ld + t * fmaf(-0.125f, uu, 0.5f);      // 2nd-order Taylor

        const float cm3 = cm * cm * cm;
        const float r   = dots * lm * cm3 * radC * ild2;
        const float d   = (pd + ld) * halfInvBin;                // bin coordinate

        const int kc = __float2int_rd(d);

        // 7-bin window kc-3..kc+3; D_j = 1 + G*e^{3j}, independent ffma-imm.
        const float G = __expf(3.0f * ((float)kc - d - 2.0f));   // MUFU.EX2
        const float D0 = fmaf(G, 1.0f,          1.0f);
        const float D1 = fmaf(G, 20.085537f,    1.0f);
        const float D2 = fmaf(G, 403.42877f,    1.0f);
        const float D3 = fmaf(G, 8103.0840f,    1.0f);
        const float D4 = fmaf(G, 162754.79f,    1.0f);
        const float D5 = fmaf(G, 3269017.4f,    1.0f);
        const float D6 = fmaf(G, 65659968.0f,   1.0f);

        // Split Montgomery: two short independent chains (one RCP each)
        const float PA1 = D0 * D1;
        const float PA2 = PA1 * D2;
        const float PA3 = PA2 * D3;                              // <= ~60
        const float PB1 = D4 * D5;
        const float PB2 = PB1 * D6;                              // <= ~5e11

        float RA = __fdividef(r, PA3);                           // MUFU.RCP
        float RB = __fdividef(r, PB2);                           // MUFU.RCP
        const float S3 = PA2 * RA;  RA *= D3;
        const float S6 = PB1 * RB;  RB *= D6;
        const float S2 = PA1 * RA;  RA *= D2;
        const float S5 = D4  * RB;  RB *= D5;
        const float S1 = D0  * RA;  RA *= D1;
        const float S4 = RB;                                     // r/D4
        const float S0 = RA;                                     // r/D0

        if (kc >= 3 && kc <= 60) {
            float* w = Wbase + ((kc - 2) << 5);   // row of bin kc-3
            w[0*32] += r  - S0;
            w[1*32] += S0 - S1;
            w[2*32] += S1 - S2;
            w[3*32] += S2 - S3;
            w[4*32] += S3 - S4;
            w[5*32] += S4 - S5;
            w[6*32] += S5 - S6;
        } else {
            const float Ss[7] = {S0, S1, S2, S3, S4, S5, S6};
            float Sm = r;
            const int b = kc - 2;
            #pragma unroll
            for (int j = 0; j < 7; ++j) {
                const int rb = min(max(b + j, 0), 65);
                Wbase[rb << 5] += Sm - Ss[j];
                Sm = Ss[j];
            }
        }
    }
}

__global__ __launch_bounds__(TPB, 12) void spad_main(
    const float* __restrict__ normals,
    const float* __restrict__ inter,
    float* __restrict__ out,
    float radC, float inv2sig2, float halfInvBin,
    float gridCS, float gridStep)
{
    // per-(warp,lane) private difference-histograms: bank == lane, conflict-free
    __shared__ float sh[NWARP][ROWS][32];

    const int tid  = threadIdx.x;
    const int lane = tid & 31;
    const int wid  = tid >> 5;

    for (int i = tid; i < NWARP * ROWS * 32; i += TPB)
        ((float*)sh)[i] = 0.0f;
    __syncthreads();

    const int cam   = blockIdx.x / CAMCHUNK;
    const int chunk = blockIdx.x % CAMCHUNK;
    // chunk 0 is half-size so its partial (and the ready flag) lands early
    const int ua    = (chunk == 0) ? 0 : 2 * chunk - 1;
    const int ub    = (chunk == 0) ? 1 : 2 * chunk + 1;
    const int qs    = (int)(((long long)NQUAD * ua) / UNITS);
    const int qe    = (int)(((long long)NQUAD * ub) / UNITS);

    const float4* n4 = (const float4*)(normals + (size_t)cam * NPIX * 3);
    const float4* p4 = (const float4*)(inter   + (size_t)cam * NPIX * 3);

    float* Wbase = &sh[wid][0][lane];

    // 2x unrolled: 8 pixels (two quads) in flight per thread
    int q = qs + tid;
    for (; q + TPB < qe; q += 2 * TPB) {
        process_quad(q,       n4, p4, Wbase, radC, inv2sig2, halfInvBin, gridCS, gridStep);
        process_quad(q + TPB, n4, p4, Wbase, radC, inv2sig2, halfInvBin, gridCS, gridStep);
    }
    if (q < qe)
        process_quad(q, n4, p4, Wbase, radC, inv2sig2, halfInvBin, gridCS, gridStep);

    __syncthreads();

    // fold warp 1 into warp 0
    float* s0 = (float*)sh;
    for (int i = tid; i < ROWS * 32; i += TPB)
        s0[i] += s0[i + ROWS * 32];
    __syncthreads();

    // lane-rotated conflict-free reduction; bins 0..63 live in rows 1..64
    float sval = 0.0f;
    if (tid < NB) {
        #pragma unroll
        for (int l = 0; l < 32; ++l)
            sval += sh[0][tid + 1][(l + tid) & 31];
    }

    if (chunk == 0) {
        // initialize out with this block's partial, then release the flag
        if (tid < NB)
            out[cam * NB + tid] = sval;
        __syncthreads();                       // all 64 stores done block-wide
        if (tid == 0) {
            unsigned int* fl = &g_ready[cam];
            asm volatile("st.release.gpu.global.u32 [%0], %1;"
                         :: "l"(fl), "r"(1u) : "memory");
        }
    } else {
        // wait until chunk 0 has initialized out[cam]
        if (tid == 0) {
            unsigned int v;
            unsigned int* fl = &g_ready[cam];
            do {
                asm volatile("ld.acquire.gpu.global.u32 %0, [%1];"
                             : "=r"(v) : "l"(fl) : "memory");
            } while (v == 0);
        }
        __syncthreads();
        if (tid < NB)
            atomicAdd(&out[cam * NB + tid], sval);
        // last adder of this camera restores the flag/counter invariant
        if (tid == 0) {
            if (atomicAdd(&g_cnt[cam], 1u) == (unsigned)(CAMCHUNK - 2)) {
                g_ready[cam] = 0;
                g_cnt[cam]   = 0;
            }
        }
    }
}

extern "C" void kernel_launch(void* const* d_in, const int* in_sizes, int n_in,
                              void* d_out, int out_size) {
    const float* normals = (const float*)d_in[0];   // [32,256,256,3]
    const float* inter   = (const float*)d_in[1];   // [32,256,256,3]
    float* out = (float*)d_out;                     // [32,64]

    const double fov    = 33.0 * M_PI / 180.0;
    const double width  = 2.0 * tan(fov / 2.0);
    const float  radC   = (float)(width * width / (M_PI * (double)NPIX));
    const double sig    = tan(21.5 * M_PI / 180.0) / 1.4;
    const float  inv2s2 = (float)(1.0 / (2.0 * sig * sig));
    const float  hib    = (float)(0.5 / 0.0136);    // (1/2) / bin_size

    // film/cos grid: linspace(-cs, cs, 256), cs = tan(fov/2)*(1 - 1/256)
    const float cs   = (float)(tan(fov / 2.0) * (1.0 - 1.0 / RES));
    const float step = (float)(2.0 * (double)cs / (RES - 1));

    spad_main<<<NCAM * CAMCHUNK, TPB>>>(normals, inter, out,
                                        radC, inv2s2, hib, cs, step);
    (void)in_sizes; (void)n_in; (void)out_size;
}